// round 14
// baseline (speedup 1.0000x reference)
#include <cuda_runtime.h>
#include <cstdint>
#include <cstdlib>

#define T_DIM 512
#define NC 65
#define NTT 64
#define KV 128
#define SS 192
#define D_DIM 256
#define DSTR 66     // dyn table row stride (NTT + 2 pad) in float2
#define SSTR 130    // sta table row stride (KV + 2 pad) in float2

#define LOG2E_F 1.4426950408889634f
#define LN2_F   0.6931471805599453f
#define KD_F (LOG2E_F / 128.0f)
#define KS_F (LOG2E_F * 0.15625f)
#define FBIAS2 8388623.0f              // 2^23 + 15

__device__ __forceinline__ float ex2f(float x) {
    float y; asm("ex2.approx.ftz.f32 %0, %1;" : "=f"(y) : "f"(x)); return y;
}

// df with sign flipped by bit31 of X (single LOP3, lut 0x78)
__device__ __forceinline__ float sxor(float df, uint32_t X) {
    uint32_t r;
    asm("lop3.b32 %0, %1, %2, 0x80000000, 0x78;"
        : "=r"(r) : "r"(__float_as_uint(df)), "r"(X));
    return __uint_as_float(r);
}

// df = clz(x+1)-16 where x = low16(X); uses y = X*2+2 = (x+1)<<1 (sign bit
// shifted out, bits16..30 of X are zero), so clz(y) = clz(x+1)-1.
// float conversion via exponent-bias trick (no I2F).
__device__ __forceinline__ float dfof(uint32_t X) {
    uint32_t y = X * 2u + 2u;                          // IMAD (fma pipe)
    uint32_t c = (uint32_t)__clz(y) | 0x4B000000u;
    return __uint_as_float(c) - FBIAS2;
}

#define DYN_UNIT2(WB, AY, PEV, SEA, SEB) {                             \
    uint32_t wb = __float_as_uint(WB);                                 \
    uint32_t XA = wb ^ wcA;                                            \
    uint32_t XB = wb ^ wcB;                                            \
    float dsA = sxor(dfof(XA), XA);                                    \
    float dsB = sxor(dfof(XB), XB);                                    \
    SEA += ex2f(fmaf(dsA, KD_F, (AY)));                                \
    SEB += ex2f(fmaf(dsB, KD_F, (AY)));                                \
    accA = fmaf(dsA, (PEV), accA);                                     \
    accB = fmaf(dsB, (PEV), accB); }

#define STA_UNIT2(WB, AY, SFA, SFB) {                                  \
    uint32_t wb = __float_as_uint(WB);                                 \
    uint32_t XA = wb ^ wcA;                                            \
    uint32_t XB = wb ^ wcB;                                            \
    SFA += ex2f(fmaf(sxor(dfof(XA), XA), KS_F, (AY)));                 \
    SFB += ex2f(fmaf(sxor(dfof(XB), XB), KS_F, (AY))); }

__global__ __launch_bounds__(288, 4)
void cg_kernel(const int* __restrict__ cur_tar, const int* __restrict__ cnc_loc,
               const int* __restrict__ sta_loc, const int* __restrict__ ttn_loc,
               const int* __restrict__ voc_loc, const float* __restrict__ sta_emb,
               const float* __restrict__ ttn_emb, float* __restrict__ out)
{
    __shared__ __align__(16) float2 s_dynT[8 * DSTR]; // [p][s] {w bits, A*KD}
    __shared__ __align__(16) float2 s_staT[8 * SSTR]; // [p][k] {w bits, A*KS}
    __shared__ float2 s_pe2[NTT / 2];
    __shared__ float  s_eu[NTT];
    __shared__ __align__(16) float s_semb[D_DIM];
    __shared__ float  s_pa[8];
    __shared__ float  s_c1;

    const int tid = threadIdx.x;
    const int t   = blockIdx.x;

    // ---- Prefetch Phase-E operands (hide 577-cycle DRAM latency under A-D) ----
    int cva = 0, cvb = 0;
    const int tar = __ldg(cur_tar + t);
    if (tid < 264) {
        const int cA = tid >> 3;
        const int p  = tid & 7;
        const int cB = (cA < 32) ? cA + 33 : cA;
        cva = __ldg(cnc_loc + ((size_t)t * NC + cA) * 8 + p);
        cvb = __ldg(cnc_loc + ((size_t)t * NC + cB) * 8 + p);
    }

    // ---------------- Phase A: pos words + A*K tables ----------------
    if (tid < SS) {
        const int s = tid;
        const int* sl   = sta_loc + (size_t)t * 8;
        const int* prow = (s < NTT) ? (ttn_loc + ((size_t)t * NTT + s) * 8)
                                    : (voc_loc + ((size_t)t * KV + (s - NTT)) * 8);
        int vv[8], ss[8];
        *(int4*)(vv)     = *(const int4*)(prow);
        *(int4*)(vv + 4) = *(const int4*)(prow + 4);
        *(int4*)(ss)     = *(const int4*)(sl);
        *(int4*)(ss + 4) = *(const int4*)(sl + 4);
        int nsp[8];
        uint32_t wbits[8];
        int sumn = 0;
        #pragma unroll
        for (int p = 0; p < 8; p++) {
            int v  = vv[p];
            int sv = ss[p];
            uint32_t av = (uint32_t)abs(v);
            uint32_t as = (uint32_t)abs(sv);
            uint32_t x  = av ^ as;                 // <= 0xFFFF
            int d   = __clz(x + 1u) - 16;          // in [-1,15]
            int n   = ((v < 0) != (sv < 0)) ? -d : d;
            nsp[p] = n; sumn += n;
            wbits[p] = av | ((v < 0) ? 0x80000000u : 0u);
        }
        #pragma unroll
        for (int p = 0; p < 8; p++) {
            float An = (float)(sumn - nsp[p]);
            float2 e;
            e.x = __uint_as_float(wbits[p]);
            if (s < NTT) { e.y = An * KD_F; s_dynT[p * DSTR + s] = e; }
            else         { e.y = An * KS_F; s_staT[p * SSTR + (s - NTT)] = e; }
        }
    }
    for (int i = tid; i < D_DIM; i += 288) s_semb[i] = sta_emb[(size_t)t * D_DIM + i];
    __syncthreads();

    // ------- Phase B: eu logits — 4 threads per dot, full unroll (MLP 16) -------
    if (tid < 256) {
        const int q = tid & 3, s = tid >> 2;
        const float4* ep = (const float4*)(ttn_emb + ((size_t)t * NTT + s) * D_DIM) + q * 16;
        const float4* sb = (const float4*)s_semb + q * 16;
        float a0 = 0.f, a1 = 0.f, a2 = 0.f, a3 = 0.f;
        #pragma unroll
        for (int i = 0; i < 16; i += 4) {
            float4 x0 = ep[i + 0], y0 = sb[i + 0];
            float4 x1 = ep[i + 1], y1 = sb[i + 1];
            float4 x2 = ep[i + 2], y2 = sb[i + 2];
            float4 x3 = ep[i + 3], y3 = sb[i + 3];
            a0 = fmaf(x0.x, y0.x, fmaf(x0.y, y0.y, fmaf(x0.z, y0.z, fmaf(x0.w, y0.w, a0))));
            a1 = fmaf(x1.x, y1.x, fmaf(x1.y, y1.y, fmaf(x1.z, y1.z, fmaf(x1.w, y1.w, a1))));
            a2 = fmaf(x2.x, y2.x, fmaf(x2.y, y2.y, fmaf(x2.z, y2.z, fmaf(x2.w, y2.w, a2))));
            a3 = fmaf(x3.x, y3.x, fmaf(x3.y, y3.y, fmaf(x3.z, y3.z, fmaf(x3.w, y3.w, a3))));
        }
        float d = (a0 + a1) + (a2 + a3);
        d += __shfl_xor_sync(0xffffffffu, d, 1);
        d += __shfl_xor_sync(0xffffffffu, d, 2);
        if (q == 0) s_eu[s] = d;
    }
    __syncthreads();

    // ---------------- Phase C: eu softmax (warp 0) ----------------
    if (tid < 32) {
        float e0 = s_eu[tid], e1 = s_eu[tid + 32];
        float mx = fmaxf(e0, e1);
        #pragma unroll
        for (int off = 16; off; off >>= 1) mx = fmaxf(mx, __shfl_xor_sync(0xffffffffu, mx, off));
        float z0 = e0 - mx, z1 = e1 - mx;
        float p0 = ex2f(z0 * LOG2E_F), p1 = ex2f(z1 * LOG2E_F);
        float Z = p0 + p1, W = p0 * z0 + p1 * z1;
        #pragma unroll
        for (int off = 16; off; off >>= 1) {
            Z += __shfl_xor_sync(0xffffffffu, Z, off);
            W += __shfl_xor_sync(0xffffffffu, W, off);
        }
        float rZ = 1.0f / Z;
        ((float*)s_pe2)[tid]      = p0 * rZ;
        ((float*)s_pe2)[tid + 32] = p1 * rZ;
        if (tid == 0) s_c1 = W * rZ - __logf(Z);
    }
    __syncthreads();

    // ------- Phase D: PA[p] (8 warps, warp=p) -------
    if (tid < 256) {
        const int p = tid >> 5, l = tid & 31;
        const float* pe = (const float*)s_pe2;
        float a = fmaf(pe[l],      s_dynT[p * DSTR + l].y,      0.f);
        a       = fmaf(pe[l + 32], s_dynT[p * DSTR + l + 32].y, a);
        #pragma unroll
        for (int off = 16; off; off >>= 1) a += __shfl_xor_sync(0xffffffffu, a, off);
        if (l == 0) s_pa[p] = a * LN2_F;
    }
    __syncthreads();

    // ---------------- Phase E: each thread handles cA and cB = cA+33 ----------------
    if (tid < 264) {
        const int cA = tid >> 3;
        const int p  = tid & 7;
        const bool has2 = (cA < 32);
        const int cB = has2 ? cA + 33 : cA;

        const uint32_t wcA = (uint32_t)abs(cva) | ((cva < 0) ? 0x80000000u : 0u);
        const uint32_t wcB = (uint32_t)abs(cvb) | ((cvb < 0) ? 0x80000000u : 0u);

        // dyn: s in [0,64), LDS.128 loads 2 entries; 4 se chains per candidate
        float seA0 = 0.f, seA1 = 0.f, seA2 = 0.f, seA3 = 0.f;
        float seB0 = 0.f, seB1 = 0.f, seB2 = 0.f, seB3 = 0.f;
        float accA = 0.f, accB = 0.f;
        const float2* dT = s_dynT + p * DSTR;
        #pragma unroll 2
        for (int s = 0; s < NTT; s += 4) {
            float4 q0 = *(const float4*)(dT + s);
            float4 q1 = *(const float4*)(dT + s + 2);
            float2 pp = s_pe2[(s >> 1) + 0];
            float2 pq = s_pe2[(s >> 1) + 1];
            DYN_UNIT2(q0.x, q0.y, pp.x, seA0, seB0);
            DYN_UNIT2(q0.z, q0.w, pp.y, seA1, seB1);
            DYN_UNIT2(q1.x, q1.y, pq.x, seA2, seB2);
            DYN_UNIT2(q1.z, q1.w, pq.y, seA3, seB3);
        }
        float seA = (seA0 + seA1) + (seA2 + seA3);
        float seB = (seB0 + seB1) + (seB2 + seB3);
        float base = s_c1 - s_pa[p];
        float lddA = base - accA * 0.0078125f + __logf(seA);
        float lddB = base - accB * 0.0078125f + __logf(seB);
        out[((size_t)t * NC + cA) * 8 + p] = lddA;
        if (has2) out[((size_t)t * NC + cB) * 8 + p] = lddB;

        // sta: k in [0,128)
        float sfA0 = 0.f, sfA1 = 0.f, sfA2 = 0.f, sfA3 = 0.f;
        float sfB0 = 0.f, sfB1 = 0.f, sfB2 = 0.f, sfB3 = 0.f;
        const float2* sT = s_staT + p * SSTR;
        #pragma unroll 2
        for (int k = 0; k < KV; k += 4) {
            float4 r0 = *(const float4*)(sT + k);
            float4 r1 = *(const float4*)(sT + k + 2);
            STA_UNIT2(r0.x, r0.y, sfA0, sfB0);
            STA_UNIT2(r0.z, r0.w, sfA1, sfB1);
            STA_UNIT2(r1.x, r1.y, sfA2, sfB2);
            STA_UNIT2(r1.z, r1.w, sfA3, sfB3);
        }
        float argA, argB;
        {
            float2 e = sT[tar];
            uint32_t wb = __float_as_uint(e.x);
            uint32_t XA = wb ^ wcA;
            uint32_t XB = wb ^ wcB;
            argA = fmaf(sxor(dfof(XA), XA), KS_F, e.y);
            argB = fmaf(sxor(dfof(XB), XB), KS_F, e.y);
        }
        float ldsA = __logf((sfA0 + sfA1) + (sfA2 + sfA3)) - LN2_F * argA;
        float ldsB = __logf((sfB0 + sfB1) + (sfB2 + sfB3)) - LN2_F * argB;
        float* outS = out + (size_t)T_DIM * NC * 8;
        outS[((size_t)t * NC + cA) * 8 + p] = ldsA;
        if (has2) outS[((size_t)t * NC + cB) * 8 + p] = ldsB;
    }
}

extern "C" void kernel_launch(void* const* d_in, const int* in_sizes, int n_in,
                              void* d_out, int out_size)
{
    const int*   cur_tar = (const int*)d_in[0];
    const int*   cnc_loc = (const int*)d_in[1];
    const int*   sta_loc = (const int*)d_in[2];
    const int*   ttn_loc = (const int*)d_in[3];
    const int*   voc_loc = (const int*)d_in[4];
    const float* sta_emb = (const float*)d_in[5];
    const float* ttn_emb = (const float*)d_in[6];
    // d_in[7] = voc_emb: unused (eu_val[:, 64:] is discarded by the reference)
    float* out = (float*)d_out;

    cg_kernel<<<T_DIM, 288>>>(cur_tar, cnc_loc, sta_loc, ttn_loc, voc_loc,
                              sta_emb, ttn_emb, out);
}

// round 15
// speedup vs baseline: 1.2945x; 1.2945x over previous
#include <cuda_runtime.h>
#include <cstdint>
#include <cstdlib>

#define T_DIM 512
#define NC 65
#define NTT 64
#define KV 128
#define SS 192
#define D_DIM 256
#define DSTR 66     // dyn table row stride (NTT + 2 pad) in float2
#define SSTR 130    // sta table row stride (KV + 2 pad) in float2

#define LOG2E_F 1.4426950408889634f
#define LN2_F   0.6931471805599453f
#define KD_F (LOG2E_F / 128.0f)        // dyn: ct = n/128 -> log2 domain
#define KS_F (LOG2E_F * 0.15625f)      // sta: logit = n*20/128
#define FBIAS2 8388623.0f              // 2^23 + 15

__device__ __forceinline__ float ex2f(float x) {
    float y; asm("ex2.approx.ftz.f32 %0, %1;" : "=f"(y) : "f"(x)); return y;
}

// df with sign flipped by bit31 of X (single LOP3, lut 0x78)
__device__ __forceinline__ float sxor(float df, uint32_t X) {
    uint32_t r;
    asm("lop3.b32 %0, %1, %2, 0x80000000, 0x78;"
        : "=r"(r) : "r"(__float_as_uint(df)), "r"(X));
    return __uint_as_float(r);
}

// df = clz(x+1)-16 where x = low16(X); y = X*2+2 = (x+1)<<1 (sign bit shifts
// out, bits16..30 of X are zero), so clz(y) = clz(x+1)-1.  IMAD lands on the
// fma pipe, balancing the alu-heavy unit.  Float conversion via exponent-bias.
__device__ __forceinline__ float dfof(uint32_t X) {
    uint32_t y = X * 2u + 2u;
    uint32_t c = (uint32_t)__clz(y) | 0x4B000000u;
    return __uint_as_float(c) - FBIAS2;
}

// Two-candidate dyn unit on explicit (w-bits, A*KD) operands
#define DYN_UNIT2(WB, AY, PEV, SEA, SEB) {                             \
    uint32_t wb = __float_as_uint(WB);                                 \
    uint32_t XA = wb ^ wcA;                                            \
    uint32_t XB = wb ^ wcB;                                            \
    float dsA = sxor(dfof(XA), XA);                                    \
    float dsB = sxor(dfof(XB), XB);                                    \
    SEA += ex2f(fmaf(dsA, KD_F, (AY)));                                \
    SEB += ex2f(fmaf(dsB, KD_F, (AY)));                                \
    accA = fmaf(dsA, (PEV), accA);                                     \
    accB = fmaf(dsB, (PEV), accB); }

#define STA_UNIT2(WB, AY, SFA, SFB) {                                  \
    uint32_t wb = __float_as_uint(WB);                                 \
    uint32_t XA = wb ^ wcA;                                            \
    uint32_t XB = wb ^ wcB;                                            \
    SFA += ex2f(fmaf(sxor(dfof(XA), XA), KS_F, (AY)));                 \
    SFB += ex2f(fmaf(sxor(dfof(XB), XB), KS_F, (AY))); }

__global__ __launch_bounds__(288, 4)
void cg_kernel(const int* __restrict__ cur_tar, const int* __restrict__ cnc_loc,
               const int* __restrict__ sta_loc, const int* __restrict__ ttn_loc,
               const int* __restrict__ voc_loc, const float* __restrict__ sta_emb,
               const float* __restrict__ ttn_emb, float* __restrict__ out)
{
    // Transposed [p][s] tables, padded so (stride*p + 2s) spreads banks by 4p.
    __shared__ __align__(16) float2 s_dynT[8 * DSTR]; // {w bits, A*KD}
    __shared__ __align__(16) float2 s_staT[8 * SSTR]; // {w bits, A*KS}
    __shared__ float2 s_pe2[NTT / 2];
    __shared__ float  s_eu[NTT];
    __shared__ float  s_semb[D_DIM];
    __shared__ float  s_pa[8];
    __shared__ float  s_c1;

    const int tid = threadIdx.x;
    const int t   = blockIdx.x;

    // ---------------- Phase A: pos words + A*K tables ----------------
    if (tid < SS) {
        const int s = tid;
        const int* sl   = sta_loc + (size_t)t * 8;
        const int* prow = (s < NTT) ? (ttn_loc + ((size_t)t * NTT + s) * 8)
                                    : (voc_loc + ((size_t)t * KV + (s - NTT)) * 8);
        int nsp[8];
        uint32_t wbits[8];
        int sumn = 0;
        #pragma unroll
        for (int p = 0; p < 8; p++) {
            int v  = prow[p];
            int sv = sl[p];
            uint32_t av = (uint32_t)abs(v);
            uint32_t as = (uint32_t)abs(sv);
            uint32_t x  = av ^ as;                 // <= 0xFFFF
            int d   = __clz(x + 1u) - 16;          // in [-1,15]
            int n   = ((v < 0) != (sv < 0)) ? -d : d;
            nsp[p] = n; sumn += n;
            wbits[p] = av | ((v < 0) ? 0x80000000u : 0u);
        }
        #pragma unroll
        for (int p = 0; p < 8; p++) {
            float An = (float)(sumn - nsp[p]);
            float2 e;
            e.x = __uint_as_float(wbits[p]);
            if (s < NTT) { e.y = An * KD_F; s_dynT[p * DSTR + s] = e; }
            else         { e.y = An * KS_F; s_staT[p * SSTR + (s - NTT)] = e; }
        }
    }
    for (int i = tid; i < D_DIM; i += 288) s_semb[i] = sta_emb[(size_t)t * D_DIM + i];
    __syncthreads();

    // ---------------- Phase B: eu logits (dot products) ----------------
    {
        const int wid = tid >> 5, lane = tid & 31;
        const float4* sb = (const float4*)s_semb;
        float4 b0 = sb[lane], b1 = sb[lane + 32];
        for (int s = wid; s < NTT; s += 9) {
            const float4* ep = (const float4*)(ttn_emb + ((size_t)t * NTT + s) * D_DIM);
            float4 a0 = ep[lane], a1 = ep[lane + 32];
            float d = a0.x * b0.x + a0.y * b0.y + a0.z * b0.z + a0.w * b0.w
                    + a1.x * b1.x + a1.y * b1.y + a1.z * b1.z + a1.w * b1.w;
            #pragma unroll
            for (int off = 16; off; off >>= 1) d += __shfl_xor_sync(0xffffffffu, d, off);
            if (lane == 0) s_eu[s] = d;
        }
    }
    __syncthreads();

    // ---------------- Phase C: eu softmax (warp 0) ----------------
    if (tid < 32) {
        float e0 = s_eu[tid], e1 = s_eu[tid + 32];
        float mx = fmaxf(e0, e1);
        #pragma unroll
        for (int off = 16; off; off >>= 1) mx = fmaxf(mx, __shfl_xor_sync(0xffffffffu, mx, off));
        float z0 = e0 - mx, z1 = e1 - mx;
        float p0 = ex2f(z0 * LOG2E_F), p1 = ex2f(z1 * LOG2E_F);
        float Z = p0 + p1, W = p0 * z0 + p1 * z1;
        #pragma unroll
        for (int off = 16; off; off >>= 1) {
            Z += __shfl_xor_sync(0xffffffffu, Z, off);
            W += __shfl_xor_sync(0xffffffffu, W, off);
        }
        float rZ = 1.0f / Z;
        ((float*)s_pe2)[tid]      = p0 * rZ;
        ((float*)s_pe2)[tid + 32] = p1 * rZ;
        if (tid == 0) s_c1 = W * rZ - __logf(Z);   // C1 = sum p*lp
    }
    __syncthreads();

    // ------- Phase D: PA[p] (8 warps, warp=p) -------
    if (tid < 256) {
        const int p = tid >> 5, l = tid & 31;
        const float* pe = (const float*)s_pe2;
        float a = fmaf(pe[l],      s_dynT[p * DSTR + l].y,        0.f);
        a       = fmaf(pe[l + 32], s_dynT[p * DSTR + l + 32].y,   a);
        #pragma unroll
        for (int off = 16; off; off >>= 1) a += __shfl_xor_sync(0xffffffffu, a, off);
        if (l == 0) s_pa[p] = a * LN2_F;
    }
    __syncthreads();

    // ---------------- Phase E: each thread handles cA and cB = cA+33 ----------------
    if (tid < 264) {
        const int cA = tid >> 3;
        const int p  = tid & 7;
        const bool has2 = (cA < 32);
        const int cB = has2 ? cA + 33 : cA;

        const int cva = cnc_loc[((size_t)t * NC + cA) * 8 + p];
        const int cvb = cnc_loc[((size_t)t * NC + cB) * 8 + p];
        const uint32_t wcA = (uint32_t)abs(cva) | ((cva < 0) ? 0x80000000u : 0u);
        const uint32_t wcB = (uint32_t)abs(cvb) | ((cvb < 0) ? 0x80000000u : 0u);

        // dyn: s in [0,64), LDS.128 loads 2 entries; 4 se chains per candidate
        float seA0 = 0.f, seA1 = 0.f, seA2 = 0.f, seA3 = 0.f;
        float seB0 = 0.f, seB1 = 0.f, seB2 = 0.f, seB3 = 0.f;
        float accA = 0.f, accB = 0.f;
        const float2* dT = s_dynT + p * DSTR;
        #pragma unroll 2
        for (int s = 0; s < NTT; s += 4) {
            float4 q0 = *(const float4*)(dT + s);       // {w[s],a[s],w[s+1],a[s+1]}
            float4 q1 = *(const float4*)(dT + s + 2);
            float2 pp = s_pe2[(s >> 1) + 0];
            float2 pq = s_pe2[(s >> 1) + 1];
            DYN_UNIT2(q0.x, q0.y, pp.x, seA0, seB0);
            DYN_UNIT2(q0.z, q0.w, pp.y, seA1, seB1);
            DYN_UNIT2(q1.x, q1.y, pq.x, seA2, seB2);
            DYN_UNIT2(q1.z, q1.w, pq.y, seA3, seB3);
        }
        float seA = (seA0 + seA1) + (seA2 + seA3);
        float seB = (seB0 + seB1) + (seB2 + seB3);
        float base = s_c1 - s_pa[p];
        float lddA = base - accA * 0.0078125f + __logf(seA);
        float lddB = base - accB * 0.0078125f + __logf(seB);
        out[((size_t)t * NC + cA) * 8 + p] = lddA;
        if (has2) out[((size_t)t * NC + cB) * 8 + p] = lddB;

        // sta: k in [0,128), LDS.128 loads 2 entries; 4 sf chains per candidate
        float sfA0 = 0.f, sfA1 = 0.f, sfA2 = 0.f, sfA3 = 0.f;
        float sfB0 = 0.f, sfB1 = 0.f, sfB2 = 0.f, sfB3 = 0.f;
        const float2* sT = s_staT + p * SSTR;
        #pragma unroll 2
        for (int k = 0; k < KV; k += 4) {
            float4 r0 = *(const float4*)(sT + k);
            float4 r1 = *(const float4*)(sT + k + 2);
            STA_UNIT2(r0.x, r0.y, sfA0, sfB0);
            STA_UNIT2(r0.z, r0.w, sfA1, sfB1);
            STA_UNIT2(r1.x, r1.y, sfA2, sfB2);
            STA_UNIT2(r1.z, r1.w, sfA3, sfB3);
        }
        const int tar = cur_tar[t];
        float argA, argB;
        {
            float2 e = sT[tar];
            uint32_t wb = __float_as_uint(e.x);
            uint32_t XA = wb ^ wcA;
            uint32_t XB = wb ^ wcB;
            argA = fmaf(sxor(dfof(XA), XA), KS_F, e.y);
            argB = fmaf(sxor(dfof(XB), XB), KS_F, e.y);
        }
        float ldsA = __logf((sfA0 + sfA1) + (sfA2 + sfA3)) - LN2_F * argA;
        float ldsB = __logf((sfB0 + sfB1) + (sfB2 + sfB3)) - LN2_F * argB;
        float* outS = out + (size_t)T_DIM * NC * 8;
        outS[((size_t)t * NC + cA) * 8 + p] = ldsA;
        if (has2) outS[((size_t)t * NC + cB) * 8 + p] = ldsB;
    }
}

extern "C" void kernel_launch(void* const* d_in, const int* in_sizes, int n_in,
                              void* d_out, int out_size)
{
    const int*   cur_tar = (const int*)d_in[0];
    const int*   cnc_loc = (const int*)d_in[1];
    const int*   sta_loc = (const int*)d_in[2];
    const int*   ttn_loc = (const int*)d_in[3];
    const int*   voc_loc = (const int*)d_in[4];
    const float* sta_emb = (const float*)d_in[5];
    const float* ttn_emb = (const float*)d_in[6];
    // d_in[7] = voc_emb: unused (eu_val[:, 64:] is discarded by the reference)
    float* out = (float*)d_out;

    cg_kernel<<<T_DIM, 288>>>(cur_tar, cnc_loc, sta_loc, ttn_loc, voc_loc,
                              sta_emb, ttn_emb, out);
}

// round 17
// speedup vs baseline: 1.3892x; 1.0732x over previous
#include <cuda_runtime.h>
#include <cstdint>
#include <cstdlib>

#define T_DIM 512
#define NC 65
#define NTT 64
#define KV 128
#define D_DIM 256
#define DSTR 66     // dyn table row stride (NTT + 2 pad) in float2
#define SSTR 130    // sta table row stride (KV + 2 pad) in float2

#define LOG2E_F 1.4426950408889634f
#define LN2_F   0.6931471805599453f
#define KD_F (LOG2E_F / 128.0f)        // dyn: ct = n/128 -> log2 domain
#define KS_F (LOG2E_F * 0.15625f)      // sta: logit = n*20/128
#define FBIAS2 8388623.0f              // 2^23 + 15

__device__ __forceinline__ float ex2f(float x) {
    float y; asm("ex2.approx.ftz.f32 %0, %1;" : "=f"(y) : "f"(x)); return y;
}

// df with sign flipped by bit31 of X (single LOP3, lut 0x78)
__device__ __forceinline__ float sxor(float df, uint32_t X) {
    uint32_t r;
    asm("lop3.b32 %0, %1, %2, 0x80000000, 0x78;"
        : "=r"(r) : "r"(__float_as_uint(df)), "r"(X));
    return __uint_as_float(r);
}

// df = clz(x+1)-16 for x = low16(X); y = X*2+2 shifts the sign bit out.
__device__ __forceinline__ float dfof(uint32_t X) {
    uint32_t y = X * 2u + 2u;
    uint32_t c = (uint32_t)__clz(y) | 0x4B000000u;
    return __uint_as_float(c) - FBIAS2;
}

#define DYN_UNIT2(WB, AY, PEV, SEA, SEB) {                             \
    uint32_t wb = __float_as_uint(WB);                                 \
    uint32_t XA = wb ^ wcA;                                            \
    uint32_t XB = wb ^ wcB;                                            \
    float dsA = sxor(dfof(XA), XA);                                    \
    float dsB = sxor(dfof(XB), XB);                                    \
    SEA += ex2f(fmaf(dsA, KD_F, (AY)));                                \
    SEB += ex2f(fmaf(dsB, KD_F, (AY)));                                \
    accA = fmaf(dsA, (PEV), accA);                                     \
    accB = fmaf(dsB, (PEV), accB); }

#define STA_UNIT2(WB, AY, SFA, SFB) {                                  \
    uint32_t wb = __float_as_uint(WB);                                 \
    uint32_t XA = wb ^ wcA;                                            \
    uint32_t XB = wb ^ wcB;                                            \
    SFA += ex2f(fmaf(sxor(dfof(XA), XA), KS_F, (AY)));                 \
    SFB += ex2f(fmaf(sxor(dfof(XB), XB), KS_F, (AY))); }

// Build one table row: pos row vs sta row -> {w bits, A*K} for 8 p's.
__device__ __forceinline__ void build_row(const int* __restrict__ prow,
                                          const int* __restrict__ sl,
                                          float2* __restrict__ dst, int stride,
                                          float K) {
    int nsp[8];
    uint32_t wbits[8];
    int sumn = 0;
    #pragma unroll
    for (int p = 0; p < 8; p++) {
        int v  = prow[p];
        int sv = sl[p];
        uint32_t av = (uint32_t)abs(v);
        uint32_t as = (uint32_t)abs(sv);
        uint32_t x  = av ^ as;
        int d   = __clz(x + 1u) - 16;
        int n   = ((v < 0) != (sv < 0)) ? -d : d;
        nsp[p] = n; sumn += n;
        wbits[p] = av | ((v < 0) ? 0x80000000u : 0u);
    }
    #pragma unroll
    for (int p = 0; p < 8; p++) {
        float2 e;
        e.x = __uint_as_float(wbits[p]);
        e.y = (float)(sumn - nsp[p]) * K;
        dst[p * stride] = e;
    }
}

__global__ __launch_bounds__(288, 5)
void cg_kernel(const int* __restrict__ cur_tar, const int* __restrict__ cnc_loc,
               const int* __restrict__ sta_loc, const int* __restrict__ ttn_loc,
               const int* __restrict__ voc_loc, const float* __restrict__ sta_emb,
               const float* __restrict__ ttn_emb, float* __restrict__ out)
{
    // One table buffer, reused per role (roles are block-uniform).
    __shared__ __align__(16) float2 s_tab[8 * SSTR];   // sta layout is the larger
    __shared__ float2 s_pe2[NTT / 2];
    __shared__ float  s_eu[NTT];
    __shared__ float  s_semb[D_DIM];
    __shared__ float  s_pa[8];
    __shared__ float  s_c1;

    const int tid = threadIdx.x;
    const int bid = blockIdx.x;

    if (bid < T_DIM) {
        // ================= STA role (long; scheduled first) =================
        const int t = bid;

        if (tid < KV) {
            build_row(voc_loc + ((size_t)t * KV + tid) * 8,
                      sta_loc + (size_t)t * 8,
                      s_tab + tid, SSTR, KS_F);
        }
        __syncthreads();

        if (tid < 264) {
            const int cA = tid >> 3;
            const int p  = tid & 7;
            const bool has2 = (cA < 32);
            const int cB = has2 ? cA + 33 : cA;

            const int cva = cnc_loc[((size_t)t * NC + cA) * 8 + p];
            const int cvb = cnc_loc[((size_t)t * NC + cB) * 8 + p];
            const uint32_t wcA = (uint32_t)abs(cva) | ((cva < 0) ? 0x80000000u : 0u);
            const uint32_t wcB = (uint32_t)abs(cvb) | ((cvb < 0) ? 0x80000000u : 0u);

            float sfA0 = 0.f, sfA1 = 0.f, sfA2 = 0.f, sfA3 = 0.f;
            float sfB0 = 0.f, sfB1 = 0.f, sfB2 = 0.f, sfB3 = 0.f;
            const float2* sT = s_tab + p * SSTR;
            #pragma unroll 2
            for (int k = 0; k < KV; k += 4) {
                float4 r0 = *(const float4*)(sT + k);
                float4 r1 = *(const float4*)(sT + k + 2);
                STA_UNIT2(r0.x, r0.y, sfA0, sfB0);
                STA_UNIT2(r0.z, r0.w, sfA1, sfB1);
                STA_UNIT2(r1.x, r1.y, sfA2, sfB2);
                STA_UNIT2(r1.z, r1.w, sfA3, sfB3);
            }
            const int tar = cur_tar[t];
            float argA, argB;
            {
                float2 e = sT[tar];
                uint32_t wb = __float_as_uint(e.x);
                uint32_t XA = wb ^ wcA;
                uint32_t XB = wb ^ wcB;
                argA = fmaf(sxor(dfof(XA), XA), KS_F, e.y);
                argB = fmaf(sxor(dfof(XB), XB), KS_F, e.y);
            }
            float ldsA = __logf((sfA0 + sfA1) + (sfA2 + sfA3)) - LN2_F * argA;
            float ldsB = __logf((sfB0 + sfB1) + (sfB2 + sfB3)) - LN2_F * argB;
            float* outS = out + (size_t)T_DIM * NC * 8;
            outS[((size_t)t * NC + cA) * 8 + p] = ldsA;
            if (has2) outS[((size_t)t * NC + cB) * 8 + p] = ldsB;
        }
    } else {
        // ================= DYN role =================
        const int t = bid - T_DIM;

        if (tid < NTT) {
            build_row(ttn_loc + ((size_t)t * NTT + tid) * 8,
                      sta_loc + (size_t)t * 8,
                      s_tab + tid, DSTR, KD_F);
        }
        for (int i = tid; i < D_DIM; i += 288) s_semb[i] = sta_emb[(size_t)t * D_DIM + i];
        __syncthreads();

        // Phase B: eu logits (9 warps)
        {
            const int wid = tid >> 5, lane = tid & 31;
            const float4* sb = (const float4*)s_semb;
            float4 b0 = sb[lane], b1 = sb[lane + 32];
            for (int s = wid; s < NTT; s += 9) {
                const float4* ep = (const float4*)(ttn_emb + ((size_t)t * NTT + s) * D_DIM);
                float4 a0 = ep[lane], a1 = ep[lane + 32];
                float d = a0.x * b0.x + a0.y * b0.y + a0.z * b0.z + a0.w * b0.w
                        + a1.x * b1.x + a1.y * b1.y + a1.z * b1.z + a1.w * b1.w;
                #pragma unroll
                for (int off = 16; off; off >>= 1) d += __shfl_xor_sync(0xffffffffu, d, off);
                if (lane == 0) s_eu[s] = d;
            }
        }
        __syncthreads();

        // Phase C: eu softmax (warp 0)
        if (tid < 32) {
            float e0 = s_eu[tid], e1 = s_eu[tid + 32];
            float mx = fmaxf(e0, e1);
            #pragma unroll
            for (int off = 16; off; off >>= 1) mx = fmaxf(mx, __shfl_xor_sync(0xffffffffu, mx, off));
            float z0 = e0 - mx, z1 = e1 - mx;
            float p0 = ex2f(z0 * LOG2E_F), p1 = ex2f(z1 * LOG2E_F);
            float Z = p0 + p1, W = p0 * z0 + p1 * z1;
            #pragma unroll
            for (int off = 16; off; off >>= 1) {
                Z += __shfl_xor_sync(0xffffffffu, Z, off);
                W += __shfl_xor_sync(0xffffffffu, W, off);
            }
            float rZ = 1.0f / Z;
            ((float*)s_pe2)[tid]      = p0 * rZ;
            ((float*)s_pe2)[tid + 32] = p1 * rZ;
            if (tid == 0) s_c1 = W * rZ - __logf(Z);
        }
        __syncthreads();

        // Phase D: PA[p] (8 warps, warp=p)
        if (tid < 256) {
            const int p = tid >> 5, l = tid & 31;
            const float* pe = (const float*)s_pe2;
            float a = fmaf(pe[l],      s_tab[p * DSTR + l].y,      0.f);
            a       = fmaf(pe[l + 32], s_tab[p * DSTR + l + 32].y, a);
            #pragma unroll
            for (int off = 16; off; off >>= 1) a += __shfl_xor_sync(0xffffffffu, a, off);
            if (l == 0) s_pa[p] = a * LN2_F;
        }
        __syncthreads();

        // Phase E-dyn
        if (tid < 264) {
            const int cA = tid >> 3;
            const int p  = tid & 7;
            const bool has2 = (cA < 32);
            const int cB = has2 ? cA + 33 : cA;

            const int cva = cnc_loc[((size_t)t * NC + cA) * 8 + p];
            const int cvb = cnc_loc[((size_t)t * NC + cB) * 8 + p];
            const uint32_t wcA = (uint32_t)abs(cva) | ((cva < 0) ? 0x80000000u : 0u);
            const uint32_t wcB = (uint32_t)abs(cvb) | ((cvb < 0) ? 0x80000000u : 0u);

            float seA0 = 0.f, seA1 = 0.f, seA2 = 0.f, seA3 = 0.f;
            float seB0 = 0.f, seB1 = 0.f, seB2 = 0.f, seB3 = 0.f;
            float accA = 0.f, accB = 0.f;
            const float2* dT = s_tab + p * DSTR;
            #pragma unroll 2
            for (int s = 0; s < NTT; s += 4) {
                float4 q0 = *(const float4*)(dT + s);
                float4 q1 = *(const float4*)(dT + s + 2);
                float2 pp = s_pe2[(s >> 1) + 0];
                float2 pq = s_pe2[(s >> 1) + 1];
                DYN_UNIT2(q0.x, q0.y, pp.x, seA0, seB0);
                DYN_UNIT2(q0.z, q0.w, pp.y, seA1, seB1);
                DYN_UNIT2(q1.x, q1.y, pq.x, seA2, seB2);
                DYN_UNIT2(q1.z, q1.w, pq.y, seA3, seB3);
            }
            float seA = (seA0 + seA1) + (seA2 + seA3);
            float seB = (seB0 + seB1) + (seB2 + seB3);
            float base = s_c1 - s_pa[p];
            float lddA = base - accA * 0.0078125f + __logf(seA);
            float lddB = base - accB * 0.0078125f + __logf(seB);
            out[((size_t)t * NC + cA) * 8 + p] = lddA;
            if (has2) out[((size_t)t * NC + cB) * 8 + p] = lddB;
        }
    }
}

extern "C" void kernel_launch(void* const* d_in, const int* in_sizes, int n_in,
                              void* d_out, int out_size)
{
    const int*   cur_tar = (const int*)d_in[0];
    const int*   cnc_loc = (const int*)d_in[1];
    const int*   sta_loc = (const int*)d_in[2];
    const int*   ttn_loc = (const int*)d_in[3];
    const int*   voc_loc = (const int*)d_in[4];
    const float* sta_emb = (const float*)d_in[5];
    const float* ttn_emb = (const float*)d_in[6];
    // d_in[7] = voc_emb: unused (eu_val[:, 64:] is discarded by the reference)
    float* out = (float*)d_out;

    cg_kernel<<<T_DIM * 2, 288>>>(cur_tar, cnc_loc, sta_loc, ttn_loc, voc_loc,
                                  sta_emb, ttn_emb, out);
}